// round 9
// baseline (speedup 1.0000x reference)
#include <cuda_runtime.h>
#include <math.h>
#include <stdint.h>

// Problem dims
#define BATCH 128
#define TT    512
#define DIM   512
#define HDIM  512
#define ODIM  256
#define NCOL  1536   // 3*HDIM

// Recurrence partition: 4 row-groups x 32 rows; 32 CTAs per group (column slices)
#define NG  4
#define RG  32
#define NC  32
#define NCTA (NG*NC)
#define NTH 512      // 16 warps

#define RZ_COLS 32   // pre-activation columns in [0,1024) per CTA
#define XS_COLS 16   // hdim slice of [1024,1536) per CTA
#define XO_COLS 8    // output columns of Wxo per CTA

typedef unsigned long long u64;

// smem: only the k-split reduction buffer. 8192 u64 = 64KB -> L1 carveout ~164KB
#define RED_U64 8192
#define SMEM_BYTES (RED_U64 * 8)

__device__ __forceinline__ u64 pack2(float lo, float hi) {
    u64 r; asm("mov.b64 %0,{%1,%2};" : "=l"(r) : "f"(lo), "f"(hi)); return r;
}
__device__ __forceinline__ void unpack2(u64 v, float& lo, float& hi) {
    asm("mov.b64 {%0,%1},%2;" : "=f"(lo), "=f"(hi) : "l"(v));
}
__device__ __forceinline__ void fma2(u64& d, u64 a, u64 b) {
    asm("fma.rn.f32x2 %0,%1,%2,%0;" : "+l"(d) : "l"(a), "l"(b));
}
__device__ __forceinline__ u64 add2(u64 a, u64 b) {
    u64 r; asm("add.rn.f32x2 %0,%1,%2;" : "=l"(r) : "l"(a), "l"(b)); return r;
}
__device__ __forceinline__ u64 dup2(float w) { return pack2(w, w); }

// ---------------- device scratch ----------------
__device__ float g_hV[(size_t)TT * BATCH * NCOL];  // precomputed hV[t][b][j]
// group-local, column-major exchange buffers: [group][col][row-pair] as packed u64
__device__ u64 g_x [NG][ODIM][RG/2];
__device__ u64 g_s [NG][HDIM][RG/2];
__device__ u64 g_rs[NG][HDIM][RG/2];
__device__ u64 g_z [NG][HDIM][RG/2];
__device__ unsigned g_bar[NG];

__device__ __forceinline__ float sigf(float x) { return 1.0f / (1.0f + expf(-x)); }

// ---------------- hV GEMM (f32x2) ----------------
#define GT_N 128
#define GT_K 8
__global__ void __launch_bounds__(256, 2)
hv_gemm(const float* __restrict__ H,
        const float* __restrict__ Vr,
        const float* __restrict__ Vz,
        const float* __restrict__ Vs) {
    if (blockIdx.x == 0 && blockIdx.y == 0 && threadIdx.x < NG)
        g_bar[threadIdx.x] = 0u;

    int t  = blockIdx.y;
    int jt = blockIdx.x;
    const float* V = (jt < 4) ? Vr : ((jt < 8) ? Vz : Vs);
    int col0 = (jt & 3) * GT_N;
    const float* A = H + (size_t)(TT - 1 - t) * DIM;

    __shared__ float Ash[GT_K][BATCH + 4];
    __shared__ float Bsh[GT_K][GT_N];

    int tx = threadIdx.x & 15, ty = threadIdx.x >> 4;
    u64 acc[4][8];
    #pragma unroll
    for (int i = 0; i < 4; i++)
        #pragma unroll
        for (int j = 0; j < 8; j++) acc[i][j] = 0ull;

    for (int k0 = 0; k0 < DIM; k0 += GT_K) {
        for (int i = threadIdx.x; i < BATCH * GT_K; i += 256) {
            int bb = i >> 3, dd = i & 7;
            Ash[dd][bb] = A[(size_t)bb * (TT * DIM) + k0 + dd];
        }
        for (int i = threadIdx.x; i < GT_K * GT_N; i += 256) {
            int dd = i >> 7, jj = i & 127;
            Bsh[dd][jj] = V[(size_t)(k0 + dd) * HDIM + col0 + jj];
        }
        __syncthreads();
        #pragma unroll
        for (int kk = 0; kk < GT_K; kk++) {
            const u64* ap0 = (const u64*)&Ash[kk][ty * 4];
            const u64* ap1 = (const u64*)&Ash[kk][64 + ty * 4];
            u64 av[4] = { ap0[0], ap0[1], ap1[0], ap1[1] };
            u64 bv[8];
            #pragma unroll
            for (int j = 0; j < 8; j++) {
                float b = (j < 4) ? Bsh[kk][tx * 4 + j] : Bsh[kk][64 + tx * 4 + (j - 4)];
                bv[j] = dup2(b);
            }
            #pragma unroll
            for (int i = 0; i < 4; i++)
                #pragma unroll
                for (int j = 0; j < 8; j++)
                    fma2(acc[i][j], av[i], bv[j]);
        }
        __syncthreads();
    }
    float* outp = g_hV + (size_t)t * BATCH * NCOL + jt * GT_N;
    int rowb[4] = { ty * 4, ty * 4 + 2, 64 + ty * 4, 64 + ty * 4 + 2 };
    #pragma unroll
    for (int i = 0; i < 4; i++)
        #pragma unroll
        for (int j = 0; j < 8; j++) {
            float lo, hi; unpack2(acc[i][j], lo, hi);
            int jc = (j < 4) ? (tx * 4 + j) : (64 + tx * 4 + (j - 4));
            outp[(size_t)rowb[i] * NCOL + jc]       = lo;
            outp[(size_t)(rowb[i] + 1) * NCOL + jc] = hi;
        }
}

// ---------------- group barrier (acquire/release) ----------------
__device__ __forceinline__ void group_barrier(int g, unsigned* target) {
    __syncthreads();
    if (threadIdx.x == 0) {
        unsigned tg = (*target += NC);
        asm volatile("red.release.gpu.global.add.u32 [%0], 1;"
                     :: "l"(&g_bar[g]) : "memory");
        unsigned v;
        do {
            asm volatile("ld.acquire.gpu.global.u32 %0, [%1];"
                         : "=r"(v) : "l"(&g_bar[g]) : "memory");
        } while (v < tg);
    }
    __syncthreads();
}

// ---------------- persistent recurrence kernel: 128 CTAs x 512 threads ----------------
__global__ void __launch_bounds__(NTH, 1)
recur_kernel(const float* __restrict__ H,   // for x0
             const float* __restrict__ W,   // [256][1536]
             const float* __restrict__ Bb,  // [1536]
             const float* __restrict__ U,   // [512][1536]
             const float* __restrict__ Wx,  // [512][768], Wxo = cols [0,256)
             const float* __restrict__ bx,  // [256]
             float* __restrict__ out)       // [128][512][256]
{
    extern __shared__ u64 red64[];          // 8192 u64

    const int cta = blockIdx.x;
    const int g   = cta >> 5;
    const int c   = cta & 31;
    const int tid = threadIdx.x;
    const int row0 = g * RG;

    const int jrz = c * RZ_COLS;
    const int kcs = c * XS_COLS;
    const int o0  = c * XO_COLS;

    const int lane = tid & 31;
    const int wrp  = tid >> 5;

    // consumer mapping (thread -> (col, row-pair))
    const int ccol = tid >> 4;     // 0..31
    const int crp  = tid & 15;     // 0..15
    const int cr0  = 2 * crp;

    unsigned bar_target = 0;

    // hoisted biases
    const float biasA1 = __ldg(Bb + jrz + ccol);
    const float biasA2 = (tid < 256) ? __ldg(Bb + 1024 + kcs + ccol) : 0.0f;
    const float biasC  = (tid < 128) ? __ldg(bx + o0 + ccol) : 0.0f;

    // Initial staging: this CTA's slice of x0 from H; its slice of s = 0
    for (int i = tid; i < XO_COLS * 16; i += NTH) {
        int col = o0 + (i >> 4); int q = i & 15;
        const float* h0 = H + ((size_t)(row0 + 2 * q)     * TT + (TT - 1)) * DIM;
        const float* h1 = H + ((size_t)(row0 + 2 * q + 1) * TT + (TT - 1)) * DIM;
        g_x[g][col][q] = pack2(h0[col] + h0[col + ODIM], h1[col] + h1[col + ODIM]);
    }
    for (int i = tid; i < XS_COLS * 16; i += NTH) {
        int col = kcs + (i >> 4);
        g_s[g][col][i & 15] = 0ull;
    }
    group_barrier(g, &bar_target);

    for (int t = 0; t < TT; t++) {
        const float* hvt = g_hV + (size_t)t * BATCH * NCOL;

        // --------- per-thread epilogue prefetches (overlap with A GEMVs) ---------
        float hvA_lo, hvA_hi, hv2_lo = 0.f, hv2_hi = 0.f;
        u64 soldA = 0ull, soldB = 0ull;
        {
            const float* p = hvt + (size_t)(row0 + cr0) * NCOL + jrz + ccol;
            hvA_lo = __ldcs(p);
            hvA_hi = __ldcs(p + NCOL);
            if (tid < 256) {
                const float* p2 = hvt + (size_t)(row0 + cr0) * NCOL + 1024 + kcs + ccol;
                hv2_lo = __ldcs(p2);
                hv2_hi = __ldcs(p2 + NCOL);
                soldB  = __ldcg(&g_s[g][kcs + ccol][crp]);
            }
            if (jrz < HDIM) soldA = __ldcg(&g_s[g][jrz + ccol][crp]);
        }

        //==================== A1 GEMV: j in [0,1024), K=768 ====================
        // warp = ch(2 col-halves of 16) x kq(8-way k-split of 96)
        // lane = cg(4 col-groups of 4) x rg(8 row-groups of 4)
        {
            int ch = wrp & 1, kq = wrp >> 1;
            int cg = lane & 3, rg = lane >> 2;
            int jl = ch * 16 + cg * 4;
            int j0 = jrz + jl;
            int rp = rg * 2;      // u64 row-pair base

            u64 acc[4][2];
            #pragma unroll
            for (int ci = 0; ci < 4; ci++) { acc[ci][0] = 0ull; acc[ci][1] = 0ull; }

            int k0 = kq * 96, k1 = k0 + 96;
            int ke = (k1 < 256) ? k1 : 256;          // x part (W rows)
            const float* wp = W + (size_t)k0 * NCOL + j0;
            #pragma unroll 8
            for (int k = k0; k < ke; k++, wp += NCOL) {
                float4 wv = __ldg((const float4*)wp);
                u64 a0 = __ldcg(&g_x[g][k][rp]);
                u64 a1 = __ldcg(&g_x[g][k][rp + 1]);
                u64 w0 = dup2(wv.x), w1 = dup2(wv.y), w2 = dup2(wv.z), w3 = dup2(wv.w);
                fma2(acc[0][0], a0, w0); fma2(acc[0][1], a1, w0);
                fma2(acc[1][0], a0, w1); fma2(acc[1][1], a1, w1);
                fma2(acc[2][0], a0, w2); fma2(acc[2][1], a1, w2);
                fma2(acc[3][0], a0, w3); fma2(acc[3][1], a1, w3);
            }
            int kb = (k0 > 256) ? k0 : 256;          // s part (U rows)
            const float* up = U + (size_t)(kb - 256) * NCOL + j0;
            #pragma unroll 8
            for (int k = kb; k < k1; k++, up += NCOL) {
                float4 wv = __ldg((const float4*)up);
                u64 a0 = __ldcg(&g_s[g][k - 256][rp]);
                u64 a1 = __ldcg(&g_s[g][k - 256][rp + 1]);
                u64 w0 = dup2(wv.x), w1 = dup2(wv.y), w2 = dup2(wv.z), w3 = dup2(wv.w);
                fma2(acc[0][0], a0, w0); fma2(acc[0][1], a1, w0);
                fma2(acc[1][0], a0, w1); fma2(acc[1][1], a1, w1);
                fma2(acc[2][0], a0, w2); fma2(acc[2][1], a1, w2);
                fma2(acc[3][0], a0, w3); fma2(acc[3][1], a1, w3);
            }
            int base = kq * 512;
            #pragma unroll
            for (int ci = 0; ci < 4; ci++)
                #pragma unroll
                for (int p = 0; p < 2; p++) {
                    int sidx = (jl + ci) * 16 + ((rg * 2 + p + cg * 4) & 15);
                    red64[base + sidx] = acc[ci][p];
                }
        }

        //==================== A2 GEMV: j in [1024,1536), K=256 ====================
        // warp = kq(16-way split of 16); lane = cg(4 col-groups of 4) x rg(8)
        {
            int kq = wrp;
            int cg = lane & 3, rg = lane >> 2;
            int jl = cg * 4;
            int j0 = 1024 + kcs + jl;
            int rp = rg * 2;

            u64 acc[4][2];
            #pragma unroll
            for (int ci = 0; ci < 4; ci++) { acc[ci][0] = 0ull; acc[ci][1] = 0ull; }

            int k0 = kq * 16;
            const float* wp = W + (size_t)k0 * NCOL + j0;
            #pragma unroll 8
            for (int k = k0; k < k0 + 16; k++, wp += NCOL) {
                float4 wv = __ldg((const float4*)wp);
                u64 a0 = __ldcg(&g_x[g][k][rp]);
                u64 a1 = __ldcg(&g_x[g][k][rp + 1]);
                u64 w0 = dup2(wv.x), w1 = dup2(wv.y), w2 = dup2(wv.z), w3 = dup2(wv.w);
                fma2(acc[0][0], a0, w0); fma2(acc[0][1], a1, w0);
                fma2(acc[1][0], a0, w1); fma2(acc[1][1], a1, w1);
                fma2(acc[2][0], a0, w2); fma2(acc[2][1], a1, w2);
                fma2(acc[3][0], a0, w3); fma2(acc[3][1], a1, w3);
            }
            int base = 4096 + kq * 256;
            #pragma unroll
            for (int ci = 0; ci < 4; ci++)
                #pragma unroll
                for (int p = 0; p < 2; p++) {
                    int sidx = (jl + ci) * 16 + ((rg * 2 + p + cg * 4) & 15);
                    red64[base + sidx] = acc[ci][p];
                }
        }
        __syncthreads();

        // --------- A1 epilogue: distributed over all 512 threads ---------
        {
            int j = jrz + ccol;
            int sidx = ccol * 16 + ((crp + ((ccol >> 2) & 3) * 4) & 15);
            u64 acc = red64[sidx];
            #pragma unroll
            for (int l = 1; l < 8; l++) acc = add2(acc, red64[l * 512 + sidx]);
            float a0, a1; unpack2(acc, a0, a1);
            a0 += biasA1 + hvA_lo;
            a1 += biasA1 + hvA_hi;
            if (jrz < HDIM) {   // whole CTA is r-gate
                float s0, s1; unpack2(soldA, s0, s1);
                g_rs[g][j][crp] = pack2(sigf(a0) * s0, sigf(a1) * s1);
            } else {            // whole CTA is z-gate
                g_z[g][j - HDIM][crp] = pack2(sigf(a0), sigf(a1));
            }
        }
        // --------- A2 epilogue -> xs stays in registers (same thread uses it in B) ---------
        float xs_lo = 0.f, xs_hi = 0.f;
        if (tid < 256) {
            int sidx = 4096 + ccol * 16 + ((crp + ((ccol >> 2) & 3) * 4) & 15);
            u64 acc = red64[sidx];
            #pragma unroll
            for (int l = 1; l < 16; l++) acc = add2(acc, red64[l * 256 + sidx]);
            float a0, a1; unpack2(acc, a0, a1);
            xs_lo = a0 + biasA2 + hv2_lo;
            xs_hi = a1 + biasA2 + hv2_hi;
        }
        group_barrier(g, &bar_target);   // r*s, z visible group-wide

        //==================== B: m = (r*s)@U_s, then s_t.  K=512 ====================
        u64 zv = 0ull;
        if (tid < 256) zv = __ldcg(&g_z[g][kcs + ccol][crp]);
        {
            int kq = wrp;
            int cg = lane & 3, rg = lane >> 2;
            int jl = cg * 4;
            int jcol = 1024 + kcs + jl;
            int rp = rg * 2;

            u64 acc[4][2];
            #pragma unroll
            for (int ci = 0; ci < 4; ci++) { acc[ci][0] = 0ull; acc[ci][1] = 0ull; }

            int k0 = kq * 32;
            const float* up = U + (size_t)k0 * NCOL + jcol;
            #pragma unroll 8
            for (int k = k0; k < k0 + 32; k++, up += NCOL) {
                float4 wv = __ldg((const float4*)up);
                u64 a0 = __ldcg(&g_rs[g][k][rp]);
                u64 a1 = __ldcg(&g_rs[g][k][rp + 1]);
                u64 w0 = dup2(wv.x), w1 = dup2(wv.y), w2 = dup2(wv.z), w3 = dup2(wv.w);
                fma2(acc[0][0], a0, w0); fma2(acc[0][1], a1, w0);
                fma2(acc[1][0], a0, w1); fma2(acc[1][1], a1, w1);
                fma2(acc[2][0], a0, w2); fma2(acc[2][1], a1, w2);
                fma2(acc[3][0], a0, w3); fma2(acc[3][1], a1, w3);
            }
            int base = kq * 256;
            #pragma unroll
            for (int ci = 0; ci < 4; ci++)
                #pragma unroll
                for (int p = 0; p < 2; p++) {
                    int sidx = (jl + ci) * 16 + ((rg * 2 + p + cg * 4) & 15);
                    red64[base + sidx] = acc[ci][p];
                }
        }
        __syncthreads();
        // --------- B epilogue: s_t (distributed, 256 threads) ---------
        if (tid < 256) {
            int kglob = kcs + ccol;
            int sidx = ccol * 16 + ((crp + ((ccol >> 2) & 3) * 4) & 15);
            u64 acc = red64[sidx];
            #pragma unroll
            for (int l = 1; l < 16; l++) acc = add2(acc, red64[l * 256 + sidx]);
            float m0, m1; unpack2(acc, m0, m1);
            float z0, z1; unpack2(zv, z0, z1);
            float s1a = tanhf(xs_lo + m0);
            float s1b = tanhf(xs_hi + m1);
            float so0, so1; unpack2(soldB, so0, so1);
            g_s[g][kglob][crp] =
                pack2((1.0f - z0) * so0 + z0 * s1a, (1.0f - z1) * so1 + z1 * s1b);
        }
        group_barrier(g, &bar_target);   // s_t visible group-wide

        //==================== C: x_t = tanh(s_t @ Wxo + bx).  K=512 ====================
        {
            int kq = wrp;
            int cg = lane & 1, rg = lane >> 1;   // 2 col-groups of 4, 16 row-pairs
            int jl = cg * 4;
            int oc0 = o0 + jl;

            u64 acc[4];
            #pragma unroll
            for (int ci = 0; ci < 4; ci++) acc[ci] = 0ull;

            int k0 = kq * 32;
            const float* wp = Wx + (size_t)k0 * (3 * ODIM) + oc0;
            #pragma unroll 8
            for (int k = k0; k < k0 + 32; k++, wp += 3 * ODIM) {
                float4 wv = __ldg((const float4*)wp);
                u64 a0 = __ldcg(&g_s[g][k][rg]);
                fma2(acc[0], a0, dup2(wv.x));
                fma2(acc[1], a0, dup2(wv.y));
                fma2(acc[2], a0, dup2(wv.z));
                fma2(acc[3], a0, dup2(wv.w));
            }
            int base = kq * 128;
            #pragma unroll
            for (int ci = 0; ci < 4; ci++) {
                int sidx = (jl + ci) * 16 + ((rg + cg * 8) & 15);
                red64[base + sidx] = acc[ci];
            }
        }
        __syncthreads();
        // --------- C epilogue: x_t (distributed, 128 threads) ---------
        if (tid < 128) {
            int oc = o0 + ccol;
            int sidx = ccol * 16 + ((crp + ((ccol >> 2) & 1) * 8) & 15);
            u64 acc = red64[sidx];
            #pragma unroll
            for (int l = 1; l < 16; l++) acc = add2(acc, red64[l * 128 + sidx]);
            float a0, a1; unpack2(acc, a0, a1);
            float x0v = tanhf(a0 + biasC);
            float x1v = tanhf(a1 + biasC);
            g_x[g][oc][crp] = pack2(x0v, x1v);
            out[((size_t)(row0 + cr0) * TT + t) * ODIM + oc]     = x0v;
            out[((size_t)(row0 + cr0 + 1) * TT + t) * ODIM + oc] = x1v;
        }
        group_barrier(g, &bar_target);   // x_t visible group-wide
    }
}

// ---------------- launch ----------------
extern "C" void kernel_launch(void* const* d_in, const int* in_sizes, int n_in,
                              void* d_out, int out_size) {
    const float* H  = (const float*)d_in[0];
    const float* W  = (const float*)d_in[1];
    const float* Bb = (const float*)d_in[2];
    const float* U  = (const float*)d_in[3];
    const float* Wx = (const float*)d_in[4];
    const float* bx = (const float*)d_in[5];
    const float* Vr = (const float*)d_in[6];
    const float* Vz = (const float*)d_in[7];
    const float* Vs = (const float*)d_in[8];
    float* out = (float*)d_out;

    cudaFuncSetAttribute(recur_kernel, cudaFuncAttributeMaxDynamicSharedMemorySize,
                         SMEM_BYTES);

    hv_gemm<<<dim3(12, 512), 256>>>(H, Vr, Vz, Vs);
    recur_kernel<<<NCTA, NTH, SMEM_BYTES>>>(H, W, Bb, U, Wx, bx, out);
}

// round 10
// speedup vs baseline: 1.0001x; 1.0001x over previous
#include <cuda_runtime.h>
#include <math.h>
#include <stdint.h>

// Problem dims
#define BATCH 128
#define TT    512
#define DIM   512
#define HDIM  512
#define ODIM  256
#define NCOL  1536   // 3*HDIM

// Recurrence partition: 4 row-groups x 32 rows; 32 CTAs per group (column slices)
#define NG  4
#define RG  32
#define NC  32
#define NCTA (NG*NC)
#define NTH 1024     // 32 warps -> 8 per SMSP for latency hiding

#define RZ_COLS 32   // pre-activation columns in [0,1024) per CTA
#define XS_COLS 16   // hdim slice of [1024,1536) per CTA
#define XO_COLS 8    // output columns of Wxo per CTA

typedef unsigned long long u64;

// smem: k-split reduction buffer. A1 uses [0,8192), A2 uses [8192,16384).
#define RED_U64 16384
#define SMEM_BYTES (RED_U64 * 8)   // 128 KB

__device__ __forceinline__ u64 pack2(float lo, float hi) {
    u64 r; asm("mov.b64 %0,{%1,%2};" : "=l"(r) : "f"(lo), "f"(hi)); return r;
}
__device__ __forceinline__ void unpack2(u64 v, float& lo, float& hi) {
    asm("mov.b64 {%0,%1},%2;" : "=f"(lo), "=f"(hi) : "l"(v));
}
__device__ __forceinline__ void fma2(u64& d, u64 a, u64 b) {
    asm("fma.rn.f32x2 %0,%1,%2,%0;" : "+l"(d) : "l"(a), "l"(b));
}
__device__ __forceinline__ u64 add2(u64 a, u64 b) {
    u64 r; asm("add.rn.f32x2 %0,%1,%2;" : "=l"(r) : "l"(a), "l"(b)); return r;
}
__device__ __forceinline__ u64 dup2(float w) { return pack2(w, w); }

// ---------------- device scratch ----------------
__device__ float g_hV[(size_t)TT * BATCH * NCOL];  // precomputed hV[t][b][j]
// group-local, column-major exchange buffers: [group][col][row-pair] as packed u64
__device__ u64 g_x [NG][ODIM][RG/2];
__device__ u64 g_s [NG][HDIM][RG/2];
__device__ u64 g_rs[NG][HDIM][RG/2];
__device__ u64 g_z [NG][HDIM][RG/2];
__device__ unsigned g_bar[NG];

__device__ __forceinline__ float sigf(float x) { return 1.0f / (1.0f + expf(-x)); }

// ---------------- hV GEMM (f32x2) ----------------
#define GT_N 128
#define GT_K 8
__global__ void __launch_bounds__(256, 2)
hv_gemm(const float* __restrict__ H,
        const float* __restrict__ Vr,
        const float* __restrict__ Vz,
        const float* __restrict__ Vs) {
    if (blockIdx.x == 0 && blockIdx.y == 0 && threadIdx.x < NG)
        g_bar[threadIdx.x] = 0u;

    int t  = blockIdx.y;
    int jt = blockIdx.x;
    const float* V = (jt < 4) ? Vr : ((jt < 8) ? Vz : Vs);
    int col0 = (jt & 3) * GT_N;
    const float* A = H + (size_t)(TT - 1 - t) * DIM;

    __shared__ float Ash[GT_K][BATCH + 4];
    __shared__ float Bsh[GT_K][GT_N];

    int tx = threadIdx.x & 15, ty = threadIdx.x >> 4;
    u64 acc[4][8];
    #pragma unroll
    for (int i = 0; i < 4; i++)
        #pragma unroll
        for (int j = 0; j < 8; j++) acc[i][j] = 0ull;

    for (int k0 = 0; k0 < DIM; k0 += GT_K) {
        for (int i = threadIdx.x; i < BATCH * GT_K; i += 256) {
            int bb = i >> 3, dd = i & 7;
            Ash[dd][bb] = A[(size_t)bb * (TT * DIM) + k0 + dd];
        }
        for (int i = threadIdx.x; i < GT_K * GT_N; i += 256) {
            int dd = i >> 7, jj = i & 127;
            Bsh[dd][jj] = V[(size_t)(k0 + dd) * HDIM + col0 + jj];
        }
        __syncthreads();
        #pragma unroll
        for (int kk = 0; kk < GT_K; kk++) {
            const u64* ap0 = (const u64*)&Ash[kk][ty * 4];
            const u64* ap1 = (const u64*)&Ash[kk][64 + ty * 4];
            u64 av[4] = { ap0[0], ap0[1], ap1[0], ap1[1] };
            u64 bv[8];
            #pragma unroll
            for (int j = 0; j < 8; j++) {
                float b = (j < 4) ? Bsh[kk][tx * 4 + j] : Bsh[kk][64 + tx * 4 + (j - 4)];
                bv[j] = dup2(b);
            }
            #pragma unroll
            for (int i = 0; i < 4; i++)
                #pragma unroll
                for (int j = 0; j < 8; j++)
                    fma2(acc[i][j], av[i], bv[j]);
        }
        __syncthreads();
    }
    float* outp = g_hV + (size_t)t * BATCH * NCOL + jt * GT_N;
    int rowb[4] = { ty * 4, ty * 4 + 2, 64 + ty * 4, 64 + ty * 4 + 2 };
    #pragma unroll
    for (int i = 0; i < 4; i++)
        #pragma unroll
        for (int j = 0; j < 8; j++) {
            float lo, hi; unpack2(acc[i][j], lo, hi);
            int jc = (j < 4) ? (tx * 4 + j) : (64 + tx * 4 + (j - 4));
            outp[(size_t)rowb[i] * NCOL + jc]       = lo;
            outp[(size_t)(rowb[i] + 1) * NCOL + jc] = hi;
        }
}

// ---------------- group barrier (acquire/release) ----------------
__device__ __forceinline__ void group_barrier(int g, unsigned* target) {
    __syncthreads();
    if (threadIdx.x == 0) {
        unsigned tg = (*target += NC);
        asm volatile("red.release.gpu.global.add.u32 [%0], 1;"
                     :: "l"(&g_bar[g]) : "memory");
        unsigned v;
        do {
            asm volatile("ld.acquire.gpu.global.u32 %0, [%1];"
                         : "=r"(v) : "l"(&g_bar[g]) : "memory");
        } while (v < tg);
    }
    __syncthreads();
}

// ---------------- persistent recurrence kernel: 128 CTAs x 1024 threads ----------------
__global__ void __launch_bounds__(NTH, 1)
recur_kernel(const float* __restrict__ H,   // for x0
             const float* __restrict__ W,   // [256][1536]
             const float* __restrict__ Bb,  // [1536]
             const float* __restrict__ U,   // [512][1536]
             const float* __restrict__ Wx,  // [512][768], Wxo = cols [0,256)
             const float* __restrict__ bx,  // [256]
             float* __restrict__ out)       // [128][512][256]
{
    extern __shared__ u64 red64[];          // 16384 u64

    const int cta = blockIdx.x;
    const int g   = cta >> 5;
    const int c   = cta & 31;
    const int tid = threadIdx.x;
    const int row0 = g * RG;

    const int jrz = c * RZ_COLS;
    const int kcs = c * XS_COLS;
    const int o0  = c * XO_COLS;

    const int lane = tid & 31;
    const int wrp  = tid >> 5;

    // consumer mapping (thread -> (col, row-pair))
    const int ccol = tid >> 4;     // 0..63
    const int crp  = tid & 15;     // 0..15
    const int cr0  = 2 * crp;

    unsigned bar_target = 0;

    // hoisted biases (guarded: only threads that use them)
    const float biasA1 = (tid < 512) ? __ldg(Bb + jrz + ccol) : 0.0f;
    const float biasA2 = (tid < 256) ? __ldg(Bb + 1024 + kcs + ccol) : 0.0f;
    const float biasC  = (tid < 128) ? __ldg(bx + o0 + ccol) : 0.0f;

    // Initial staging: this CTA's slice of x0 from H; its slice of s = 0
    for (int i = tid; i < XO_COLS * 16; i += NTH) {
        int col = o0 + (i >> 4); int q = i & 15;
        const float* h0 = H + ((size_t)(row0 + 2 * q)     * TT + (TT - 1)) * DIM;
        const float* h1 = H + ((size_t)(row0 + 2 * q + 1) * TT + (TT - 1)) * DIM;
        g_x[g][col][q] = pack2(h0[col] + h0[col + ODIM], h1[col] + h1[col + ODIM]);
    }
    for (int i = tid; i < XS_COLS * 16; i += NTH) {
        int col = kcs + (i >> 4);
        g_s[g][col][i & 15] = 0ull;
    }
    group_barrier(g, &bar_target);

    for (int t = 0; t < TT; t++) {
        const float* hvt = g_hV + (size_t)t * BATCH * NCOL;

        // --------- per-thread epilogue prefetches (overlap with A GEMVs) ---------
        float hvA_lo = 0.f, hvA_hi = 0.f, hv2_lo = 0.f, hv2_hi = 0.f;
        u64 soldA = 0ull, soldB = 0ull;
        if (tid < 512) {
            const float* p = hvt + (size_t)(row0 + cr0) * NCOL + jrz + ccol;
            hvA_lo = __ldcs(p);
            hvA_hi = __ldcs(p + NCOL);
            if (jrz < HDIM) soldA = __ldcg(&g_s[g][jrz + ccol][crp]);
            if (tid < 256) {
                const float* p2 = hvt + (size_t)(row0 + cr0) * NCOL + 1024 + kcs + ccol;
                hv2_lo = __ldcs(p2);
                hv2_hi = __ldcs(p2 + NCOL);
                soldB  = __ldcg(&g_s[g][kcs + ccol][crp]);
            }
        }

        //==================== A1 GEMV: j in [0,1024), K=768 ====================
        // warp = ch(2 col-halves of 16) x kq(16-way k-split of 48)
        // lane = cg(4 col-groups of 4) x rg(8 row-pair-groups of 2)
        {
            int ch = wrp & 1, kq = wrp >> 1;
            int cg = lane & 3, rg = lane >> 2;
            int jl = ch * 16 + cg * 4;
            int j0 = jrz + jl;
            int rp = rg * 2;      // u64 row-pair base

            u64 acc[4][2];
            #pragma unroll
            for (int ci = 0; ci < 4; ci++) { acc[ci][0] = 0ull; acc[ci][1] = 0ull; }

            int k0 = kq * 48, k1 = k0 + 48;
            int ke = (k1 < 256) ? k1 : 256;          // x part (W rows)
            const float* wp = W + (size_t)k0 * NCOL + j0;
            #pragma unroll 4
            for (int k = k0; k < ke; k++, wp += NCOL) {
                float4 wv = __ldg((const float4*)wp);
                u64 a0 = __ldcg(&g_x[g][k][rp]);
                u64 a1 = __ldcg(&g_x[g][k][rp + 1]);
                u64 w0 = dup2(wv.x), w1 = dup2(wv.y), w2 = dup2(wv.z), w3 = dup2(wv.w);
                fma2(acc[0][0], a0, w0); fma2(acc[0][1], a1, w0);
                fma2(acc[1][0], a0, w1); fma2(acc[1][1], a1, w1);
                fma2(acc[2][0], a0, w2); fma2(acc[2][1], a1, w2);
                fma2(acc[3][0], a0, w3); fma2(acc[3][1], a1, w3);
            }
            int kb = (k0 > 256) ? k0 : 256;          // s part (U rows)
            const float* up = U + (size_t)(kb - 256) * NCOL + j0;
            #pragma unroll 4
            for (int k = kb; k < k1; k++, up += NCOL) {
                float4 wv = __ldg((const float4*)up);
                u64 a0 = __ldcg(&g_s[g][k - 256][rp]);
                u64 a1 = __ldcg(&g_s[g][k - 256][rp + 1]);
                u64 w0 = dup2(wv.x), w1 = dup2(wv.y), w2 = dup2(wv.z), w3 = dup2(wv.w);
                fma2(acc[0][0], a0, w0); fma2(acc[0][1], a1, w0);
                fma2(acc[1][0], a0, w1); fma2(acc[1][1], a1, w1);
                fma2(acc[2][0], a0, w2); fma2(acc[2][1], a1, w2);
                fma2(acc[3][0], a0, w3); fma2(acc[3][1], a1, w3);
            }
            int base = kq * 512;
            #pragma unroll
            for (int ci = 0; ci < 4; ci++)
                #pragma unroll
                for (int p = 0; p < 2; p++) {
                    int sidx = (jl + ci) * 16 + ((rp + p + cg * 4) & 15);
                    red64[base + sidx] = acc[ci][p];
                }
        }

        //==================== A2 GEMV: j in [1024,1536), K=256 ====================
        // warp = kq(32-way split of 8); lane = cg(4 col-groups of 4) x rg(8)
        {
            int kq = wrp;
            int cg = lane & 3, rg = lane >> 2;
            int jl = cg * 4;
            int j0 = 1024 + kcs + jl;
            int rp = rg * 2;

            u64 acc[4][2];
            #pragma unroll
            for (int ci = 0; ci < 4; ci++) { acc[ci][0] = 0ull; acc[ci][1] = 0ull; }

            int k0 = kq * 8;
            const float* wp = W + (size_t)k0 * NCOL + j0;
            #pragma unroll 4
            for (int k = k0; k < k0 + 8; k++, wp += NCOL) {
                float4 wv = __ldg((const float4*)wp);
                u64 a0 = __ldcg(&g_x[g][k][rp]);
                u64 a1 = __ldcg(&g_x[g][k][rp + 1]);
                u64 w0 = dup2(wv.x), w1 = dup2(wv.y), w2 = dup2(wv.z), w3 = dup2(wv.w);
                fma2(acc[0][0], a0, w0); fma2(acc[0][1], a1, w0);
                fma2(acc[1][0], a0, w1); fma2(acc[1][1], a1, w1);
                fma2(acc[2][0], a0, w2); fma2(acc[2][1], a1, w2);
                fma2(acc[3][0], a0, w3); fma2(acc[3][1], a1, w3);
            }
            int base = 8192 + kq * 256;
            #pragma unroll
            for (int ci = 0; ci < 4; ci++)
                #pragma unroll
                for (int p = 0; p < 2; p++) {
                    int sidx = (jl + ci) * 16 + ((rp + p + cg * 4) & 15);
                    red64[base + sidx] = acc[ci][p];
                }
        }
        __syncthreads();

        // --------- A1 epilogue: distributed over 512 threads ---------
        if (tid < 512) {
            int j = jrz + ccol;
            int sidx = ccol * 16 + ((crp + ((ccol >> 2) & 3) * 4) & 15);
            u64 acc = red64[sidx];
            #pragma unroll
            for (int l = 1; l < 16; l++) acc = add2(acc, red64[l * 512 + sidx]);
            float a0, a1; unpack2(acc, a0, a1);
            a0 += biasA1 + hvA_lo;
            a1 += biasA1 + hvA_hi;
            if (jrz < HDIM) {   // whole CTA is r-gate
                float s0, s1; unpack2(soldA, s0, s1);
                g_rs[g][j][crp] = pack2(sigf(a0) * s0, sigf(a1) * s1);
            } else {            // whole CTA is z-gate
                g_z[g][j - HDIM][crp] = pack2(sigf(a0), sigf(a1));
            }
        }
        // --------- A2 epilogue -> xs stays in registers (same thread uses it in B) ---------
        float xs_lo = 0.f, xs_hi = 0.f;
        if (tid < 256) {
            int sidx = 8192 + ccol * 16 + ((crp + ((ccol >> 2) & 3) * 4) & 15);
            u64 acc = red64[sidx];
            #pragma unroll
            for (int l = 1; l < 32; l++) acc = add2(acc, red64[l * 256 + sidx]);
            float a0, a1; unpack2(acc, a0, a1);
            xs_lo = a0 + biasA2 + hv2_lo;
            xs_hi = a1 + biasA2 + hv2_hi;
        }
        group_barrier(g, &bar_target);   // r*s, z visible group-wide

        //==================== B: m = (r*s)@U_s, then s_t.  K=512 ====================
        u64 zv = 0ull;
        if (tid < 256) zv = __ldcg(&g_z[g][kcs + ccol][crp]);
        {
            int kq = wrp;
            int cg = lane & 3, rg = lane >> 2;
            int jl = cg * 4;
            int jcol = 1024 + kcs + jl;
            int rp = rg * 2;

            u64 acc[4][2];
            #pragma unroll
            for (int ci = 0; ci < 4; ci++) { acc[ci][0] = 0ull; acc[ci][1] = 0ull; }

            int k0 = kq * 16;
            const float* up = U + (size_t)k0 * NCOL + jcol;
            #pragma unroll 4
            for (int k = k0; k < k0 + 16; k++, up += NCOL) {
                float4 wv = __ldg((const float4*)up);
                u64 a0 = __ldcg(&g_rs[g][k][rp]);
                u64 a1 = __ldcg(&g_rs[g][k][rp + 1]);
                u64 w0 = dup2(wv.x), w1 = dup2(wv.y), w2 = dup2(wv.z), w3 = dup2(wv.w);
                fma2(acc[0][0], a0, w0); fma2(acc[0][1], a1, w0);
                fma2(acc[1][0], a0, w1); fma2(acc[1][1], a1, w1);
                fma2(acc[2][0], a0, w2); fma2(acc[2][1], a1, w2);
                fma2(acc[3][0], a0, w3); fma2(acc[3][1], a1, w3);
            }
            int base = kq * 256;
            #pragma unroll
            for (int ci = 0; ci < 4; ci++)
                #pragma unroll
                for (int p = 0; p < 2; p++) {
                    int sidx = (jl + ci) * 16 + ((rp + p + cg * 4) & 15);
                    red64[base + sidx] = acc[ci][p];
                }
        }
        __syncthreads();
        // --------- B epilogue: s_t (distributed, 256 threads) ---------
        if (tid < 256) {
            int kglob = kcs + ccol;
            int sidx = ccol * 16 + ((crp + ((ccol >> 2) & 3) * 4) & 15);
            u64 acc = red64[sidx];
            #pragma unroll
            for (int l = 1; l < 32; l++) acc = add2(acc, red64[l * 256 + sidx]);
            float m0, m1; unpack2(acc, m0, m1);
            float z0, z1; unpack2(zv, z0, z1);
            float s1a = tanhf(xs_lo + m0);
            float s1b = tanhf(xs_hi + m1);
            float so0, so1; unpack2(soldB, so0, so1);
            g_s[g][kglob][crp] =
                pack2((1.0f - z0) * so0 + z0 * s1a, (1.0f - z1) * so1 + z1 * s1b);
        }
        group_barrier(g, &bar_target);   // s_t visible group-wide

        //==================== C: x_t = tanh(s_t @ Wxo + bx).  K=512 ====================
        {
            int kq = wrp;
            int cg = lane & 1, rg = lane >> 1;   // 2 col-groups of 4, 16 row-pairs
            int jl = cg * 4;
            int oc0 = o0 + jl;

            u64 acc[4];
            #pragma unroll
            for (int ci = 0; ci < 4; ci++) acc[ci] = 0ull;

            int k0 = kq * 16;
            const float* wp = Wx + (size_t)k0 * (3 * ODIM) + oc0;
            #pragma unroll 4
            for (int k = k0; k < k0 + 16; k++, wp += 3 * ODIM) {
                float4 wv = __ldg((const float4*)wp);
                u64 a0 = __ldcg(&g_s[g][k][rg]);
                fma2(acc[0], a0, dup2(wv.x));
                fma2(acc[1], a0, dup2(wv.y));
                fma2(acc[2], a0, dup2(wv.z));
                fma2(acc[3], a0, dup2(wv.w));
            }
            int base = kq * 128;
            #pragma unroll
            for (int ci = 0; ci < 4; ci++) {
                int sidx = (jl + ci) * 16 + ((rg + cg * 8) & 15);
                red64[base + sidx] = acc[ci];
            }
        }
        __syncthreads();
        // --------- C epilogue: x_t (distributed, 128 threads) ---------
        if (tid < 128) {
            int oc = o0 + ccol;
            int sidx = ccol * 16 + ((crp + ((ccol >> 2) & 1) * 8) & 15);
            u64 acc = red64[sidx];
            #pragma unroll
            for (int l = 1; l < 32; l++) acc = add2(acc, red64[l * 128 + sidx]);
            float a0, a1; unpack2(acc, a0, a1);
            float x0v = tanhf(a0 + biasC);
            float x1v = tanhf(a1 + biasC);
            g_x[g][oc][crp] = pack2(x0v, x1v);
            out[((size_t)(row0 + cr0) * TT + t) * ODIM + oc]     = x0v;
            out[((size_t)(row0 + cr0 + 1) * TT + t) * ODIM + oc] = x1v;
        }
        group_barrier(g, &bar_target);   // x_t visible group-wide
    }
}

// ---------------- launch ----------------
extern "C" void kernel_launch(void* const* d_in, const int* in_sizes, int n_in,
                              void* d_out, int out_size) {
    const float* H  = (const float*)d_in[0];
    const float* W  = (const float*)d_in[1];
    const float* Bb = (const float*)d_in[2];
    const float* U  = (const float*)d_in[3];
    const float* Wx = (const float*)d_in[4];
    const float* bx = (const float*)d_in[5];
    const float* Vr = (const float*)d_in[6];
    const float* Vz = (const float*)d_in[7];
    const float* Vs = (const float*)d_in[8];
    float* out = (float*)d_out;

    cudaFuncSetAttribute(recur_kernel, cudaFuncAttributeMaxDynamicSharedMemorySize,
                         SMEM_BYTES);

    hv_gemm<<<dim3(12, 512), 256>>>(H, Vr, Vz, Vs);
    recur_kernel<<<NCTA, NTH, SMEM_BYTES>>>(H, W, Bb, U, Wx, bx, out);
}

// round 11
// speedup vs baseline: 1.2128x; 1.2126x over previous
#include <cuda_runtime.h>
#include <math.h>
#include <stdint.h>

// Problem dims
#define BATCH 128
#define TT    512
#define DIM   512
#define HDIM  512
#define ODIM  256
#define NCOL  1536   // 3*HDIM

// Recurrence partition: 4 row-groups x 32 rows; 32 CTAs per group (column slices)
#define NG  4
#define RG  32
#define NC  32
#define NCTA (NG*NC)
#define NTH 512      // 16 warps

#define RZ_COLS 32   // pre-activation columns in [0,1024) per CTA
#define XS_COLS 16   // hdim slice of [1024,1536) per CTA
#define XO_COLS 8    // output columns of Wxo per CTA

typedef unsigned long long u64;

// ---- dynamic smem layout (bytes) ----
// ws_rz : 768*32 f  = 98304   A1 weights (k<256: W, k>=256: U), cols jrz..jrz+31
// ws_xs : 256*16 f  = 16384   W cols 1024+kcs..+15
// ws_us : 512*16 f  = 32768   U cols 1024+kcs..+15
// ws_o  : 512*8  f  = 16384   Wx cols o0..o0+7
// red   : 8192 u64  = 65536
#define OFF_WRZ 0
#define OFF_WXS 98304
#define OFF_WUS 114688
#define OFF_WO  147456
#define OFF_RED 163840
#define SMEM_BYTES 229376

__device__ __forceinline__ u64 pack2(float lo, float hi) {
    u64 r; asm("mov.b64 %0,{%1,%2};" : "=l"(r) : "f"(lo), "f"(hi)); return r;
}
__device__ __forceinline__ void unpack2(u64 v, float& lo, float& hi) {
    asm("mov.b64 {%0,%1},%2;" : "=f"(lo), "=f"(hi) : "l"(v));
}
__device__ __forceinline__ void fma2(u64& d, u64 a, u64 b) {
    asm("fma.rn.f32x2 %0,%1,%2,%0;" : "+l"(d) : "l"(a), "l"(b));
}
__device__ __forceinline__ u64 add2(u64 a, u64 b) {
    u64 r; asm("add.rn.f32x2 %0,%1,%2;" : "=l"(r) : "l"(a), "l"(b)); return r;
}
__device__ __forceinline__ u64 dup2(float w) { return pack2(w, w); }
__device__ __forceinline__ void ldcg2(const u64* p, u64& x, u64& y) {
    asm volatile("ld.global.cg.v2.u64 {%0,%1},[%2];" : "=l"(x), "=l"(y) : "l"(p));
}

// ---------------- device scratch ----------------
__device__ float g_hV[(size_t)TT * BATCH * NCOL];  // precomputed hV[t][b][j]
// group-local, column-major exchange buffers: [group][col][row-pair], 16B aligned
__device__ __align__(16) u64 g_x [NG][ODIM][RG/2];
__device__ __align__(16) u64 g_s [NG][HDIM][RG/2];
__device__ __align__(16) u64 g_rs[NG][HDIM][RG/2];
__device__ __align__(16) u64 g_z [NG][HDIM][RG/2];
__device__ unsigned g_bar[NG];

__device__ __forceinline__ float sigf(float x) { return 1.0f / (1.0f + expf(-x)); }

// ---------------- hV GEMM (f32x2) ----------------
#define GT_N 128
#define GT_K 8
__global__ void __launch_bounds__(256, 2)
hv_gemm(const float* __restrict__ H,
        const float* __restrict__ Vr,
        const float* __restrict__ Vz,
        const float* __restrict__ Vs) {
    if (blockIdx.x == 0 && blockIdx.y == 0 && threadIdx.x < NG)
        g_bar[threadIdx.x] = 0u;

    int t  = blockIdx.y;
    int jt = blockIdx.x;
    const float* V = (jt < 4) ? Vr : ((jt < 8) ? Vz : Vs);
    int col0 = (jt & 3) * GT_N;
    const float* A = H + (size_t)(TT - 1 - t) * DIM;

    __shared__ float Ash[GT_K][BATCH + 4];
    __shared__ float Bsh[GT_K][GT_N];

    int tx = threadIdx.x & 15, ty = threadIdx.x >> 4;
    u64 acc[4][8];
    #pragma unroll
    for (int i = 0; i < 4; i++)
        #pragma unroll
        for (int j = 0; j < 8; j++) acc[i][j] = 0ull;

    for (int k0 = 0; k0 < DIM; k0 += GT_K) {
        for (int i = threadIdx.x; i < BATCH * GT_K; i += 256) {
            int bb = i >> 3, dd = i & 7;
            Ash[dd][bb] = A[(size_t)bb * (TT * DIM) + k0 + dd];
        }
        for (int i = threadIdx.x; i < GT_K * GT_N; i += 256) {
            int dd = i >> 7, jj = i & 127;
            Bsh[dd][jj] = V[(size_t)(k0 + dd) * HDIM + col0 + jj];
        }
        __syncthreads();
        #pragma unroll
        for (int kk = 0; kk < GT_K; kk++) {
            const u64* ap0 = (const u64*)&Ash[kk][ty * 4];
            const u64* ap1 = (const u64*)&Ash[kk][64 + ty * 4];
            u64 av[4] = { ap0[0], ap0[1], ap1[0], ap1[1] };
            u64 bv[8];
            #pragma unroll
            for (int j = 0; j < 8; j++) {
                float b = (j < 4) ? Bsh[kk][tx * 4 + j] : Bsh[kk][64 + tx * 4 + (j - 4)];
                bv[j] = dup2(b);
            }
            #pragma unroll
            for (int i = 0; i < 4; i++)
                #pragma unroll
                for (int j = 0; j < 8; j++)
                    fma2(acc[i][j], av[i], bv[j]);
        }
        __syncthreads();
    }
    float* outp = g_hV + (size_t)t * BATCH * NCOL + jt * GT_N;
    int rowb[4] = { ty * 4, ty * 4 + 2, 64 + ty * 4, 64 + ty * 4 + 2 };
    #pragma unroll
    for (int i = 0; i < 4; i++)
        #pragma unroll
        for (int j = 0; j < 8; j++) {
            float lo, hi; unpack2(acc[i][j], lo, hi);
            int jc = (j < 4) ? (tx * 4 + j) : (64 + tx * 4 + (j - 4));
            outp[(size_t)rowb[i] * NCOL + jc]       = lo;
            outp[(size_t)(rowb[i] + 1) * NCOL + jc] = hi;
        }
}

// ---------------- group barrier (acquire/release) ----------------
__device__ __forceinline__ void group_barrier(int g, unsigned* target) {
    __syncthreads();
    if (threadIdx.x == 0) {
        unsigned tg = (*target += NC);
        asm volatile("red.release.gpu.global.add.u32 [%0], 1;"
                     :: "l"(&g_bar[g]) : "memory");
        unsigned v;
        do {
            asm volatile("ld.acquire.gpu.global.u32 %0, [%1];"
                         : "=r"(v) : "l"(&g_bar[g]) : "memory");
        } while (v < tg);
    }
    __syncthreads();
}

// ---------------- persistent recurrence kernel: 128 CTAs x 512 threads ----------------
__global__ void __launch_bounds__(NTH, 1)
recur_kernel(const float* __restrict__ H,   // for x0
             const float* __restrict__ W,   // [256][1536]
             const float* __restrict__ Bb,  // [1536]
             const float* __restrict__ U,   // [512][1536]
             const float* __restrict__ Wx,  // [512][768], Wxo = cols [0,256)
             const float* __restrict__ bx,  // [256]
             float* __restrict__ out)       // [128][512][256]
{
    extern __shared__ char smbase[];
    float* ws_rz = (float*)(smbase + OFF_WRZ);   // [768][32]
    float* ws_xs = (float*)(smbase + OFF_WXS);   // [256][16]
    float* ws_us = (float*)(smbase + OFF_WUS);   // [512][16]
    float* ws_o  = (float*)(smbase + OFF_WO);    // [512][8]
    u64*   red   = (u64*)  (smbase + OFF_RED);   // [8192]

    const int cta = blockIdx.x;
    const int g   = cta >> 5;
    const int c   = cta & 31;
    const int tid = threadIdx.x;
    const int row0 = g * RG;

    const int jrz = c * RZ_COLS;
    const int kcs = c * XS_COLS;
    const int o0  = c * XO_COLS;

    const int lane = tid & 31;
    const int wrp  = tid >> 5;

    // consumer mapping (thread -> (col, row-pair))
    const int ccol = tid >> 4;     // 0..31
    const int crp  = tid & 15;     // 0..15
    const int cr0  = 2 * crp;

    unsigned bar_target = 0;

    // hoisted biases
    const float biasA1 = __ldg(Bb + jrz + ccol);
    const float biasA2 = (tid < 256) ? __ldg(Bb + 1024 + kcs + ccol) : 0.0f;
    const float biasC  = (tid < 128) ? __ldg(bx + o0 + ccol) : 0.0f;

    // ---- preload this CTA's weight slices into smem (once; reused 512 steps) ----
    for (int i = tid; i < 768 * 32; i += NTH) {
        int k = i >> 5, cc = i & 31;
        ws_rz[i] = (k < 256) ? __ldg(W + (size_t)k * NCOL + jrz + cc)
                             : __ldg(U + (size_t)(k - 256) * NCOL + jrz + cc);
    }
    for (int i = tid; i < 256 * 16; i += NTH) {
        int k = i >> 4, cc = i & 15;
        ws_xs[i] = __ldg(W + (size_t)k * NCOL + 1024 + kcs + cc);
    }
    for (int i = tid; i < 512 * 16; i += NTH) {
        int k = i >> 4, cc = i & 15;
        ws_us[i] = __ldg(U + (size_t)k * NCOL + 1024 + kcs + cc);
    }
    for (int i = tid; i < 512 * 8; i += NTH) {
        int k = i >> 3, cc = i & 7;
        ws_o[i] = __ldg(Wx + (size_t)k * (3 * ODIM) + o0 + cc);
    }

    // Initial staging: this CTA's slice of x0 from H; its slice of s = 0
    for (int i = tid; i < XO_COLS * 16; i += NTH) {
        int col = o0 + (i >> 4); int q = i & 15;
        const float* h0 = H + ((size_t)(row0 + 2 * q)     * TT + (TT - 1)) * DIM;
        const float* h1 = H + ((size_t)(row0 + 2 * q + 1) * TT + (TT - 1)) * DIM;
        g_x[g][col][q] = pack2(h0[col] + h0[col + ODIM], h1[col] + h1[col + ODIM]);
    }
    for (int i = tid; i < XS_COLS * 16; i += NTH) {
        int col = kcs + (i >> 4);
        g_s[g][col][i & 15] = 0ull;
    }
    group_barrier(g, &bar_target);   // also covers the smem weight preload

    for (int t = 0; t < TT; t++) {
        const float* hvt = g_hV + (size_t)t * BATCH * NCOL;

        // --------- per-thread epilogue prefetches (overlap with A GEMVs) ---------
        float hvA_lo, hvA_hi, hv2_lo = 0.f, hv2_hi = 0.f;
        u64 soldA = 0ull, soldB = 0ull;
        {
            const float* p = hvt + (size_t)(row0 + cr0) * NCOL + jrz + ccol;
            hvA_lo = __ldcs(p);
            hvA_hi = __ldcs(p + NCOL);
            if (jrz < HDIM) soldA = __ldcg(&g_s[g][jrz + ccol][crp]);
            if (tid < 256) {
                const float* p2 = hvt + (size_t)(row0 + cr0) * NCOL + 1024 + kcs + ccol;
                hv2_lo = __ldcs(p2);
                hv2_hi = __ldcs(p2 + NCOL);
                soldB  = __ldcg(&g_s[g][kcs + ccol][crp]);
            }
        }

        //==================== A1 GEMV: 32 cols, 32 rows, K=768 ====================
        // warp = kq (16-way split of 48); lane = cg(8 col-groups of 4) x rg(4 row-groups of 8)
        {
            int kq = wrp;
            int cg = lane & 7, rg = lane >> 3;
            int rp4 = rg * 4;                       // u64 row-pair base (4 pairs = 8 rows)
            const float* wrow = ws_rz + cg * 4;

            u64 acc[4][4];
            #pragma unroll
            for (int ci = 0; ci < 4; ci++)
                #pragma unroll
                for (int q = 0; q < 4; q++) acc[ci][q] = 0ull;

            int k0 = kq * 48, k1 = k0 + 48;
            int ke = (k1 < 256) ? k1 : 256;          // x part
            #pragma unroll 4
            for (int k = k0; k < ke; k++) {
                float4 wv = *(const float4*)(wrow + k * 32);
                u64 a0, a1, a2, a3;
                ldcg2(&g_x[g][k][rp4], a0, a1);
                ldcg2(&g_x[g][k][rp4 + 2], a2, a3);
                u64 w;
                w = dup2(wv.x); fma2(acc[0][0],a0,w); fma2(acc[0][1],a1,w); fma2(acc[0][2],a2,w); fma2(acc[0][3],a3,w);
                w = dup2(wv.y); fma2(acc[1][0],a0,w); fma2(acc[1][1],a1,w); fma2(acc[1][2],a2,w); fma2(acc[1][3],a3,w);
                w = dup2(wv.z); fma2(acc[2][0],a0,w); fma2(acc[2][1],a1,w); fma2(acc[2][2],a2,w); fma2(acc[2][3],a3,w);
                w = dup2(wv.w); fma2(acc[3][0],a0,w); fma2(acc[3][1],a1,w); fma2(acc[3][2],a2,w); fma2(acc[3][3],a3,w);
            }
            int kb = (k0 > 256) ? k0 : 256;          // s part
            #pragma unroll 4
            for (int k = kb; k < k1; k++) {
                float4 wv = *(const float4*)(wrow + k * 32);
                u64 a0, a1, a2, a3;
                ldcg2(&g_s[g][k - 256][rp4], a0, a1);
                ldcg2(&g_s[g][k - 256][rp4 + 2], a2, a3);
                u64 w;
                w = dup2(wv.x); fma2(acc[0][0],a0,w); fma2(acc[0][1],a1,w); fma2(acc[0][2],a2,w); fma2(acc[0][3],a3,w);
                w = dup2(wv.y); fma2(acc[1][0],a0,w); fma2(acc[1][1],a1,w); fma2(acc[1][2],a2,w); fma2(acc[1][3],a3,w);
                w = dup2(wv.z); fma2(acc[2][0],a0,w); fma2(acc[2][1],a1,w); fma2(acc[2][2],a2,w); fma2(acc[2][3],a3,w);
                w = dup2(wv.w); fma2(acc[3][0],a0,w); fma2(acc[3][1],a1,w); fma2(acc[3][2],a2,w); fma2(acc[3][3],a3,w);
            }
            #pragma unroll
            for (int ci = 0; ci < 4; ci++)
                #pragma unroll
                for (int q = 0; q < 4; q++) {
                    int col = cg * 4 + ci, rp = rp4 + q;
                    red[kq * 512 + rp * 32 + ((col + rp + (rp >> 2)) & 31)] = acc[ci][q];
                }
        }
        __syncthreads();
        // --------- A1 epilogue: distributed over all 512 threads ---------
        {
            int j = jrz + ccol;
            int sidx = crp * 32 + ((ccol + crp + (crp >> 2)) & 31);
            u64 acc = red[sidx];
            #pragma unroll
            for (int l = 1; l < 16; l++) acc = add2(acc, red[l * 512 + sidx]);
            float a0, a1; unpack2(acc, a0, a1);
            a0 += biasA1 + hvA_lo;
            a1 += biasA1 + hvA_hi;
            if (jrz < HDIM) {   // whole CTA is r-gate
                float s0, s1; unpack2(soldA, s0, s1);
                g_rs[g][j][crp] = pack2(sigf(a0) * s0, sigf(a1) * s1);
            } else {            // whole CTA is z-gate
                g_z[g][j - HDIM][crp] = pack2(sigf(a0), sigf(a1));
            }
        }
        __syncthreads();   // red free for A2

        //==================== A2 GEMV: 16 cols, 32 rows, K=256 ====================
        // warp = kq (16-way of 16); lane = cg(4 col-groups of 4) x rg(8 row-pair-groups of 2)
        {
            int kq = wrp;
            int cg = lane & 3, rg = lane >> 2;
            int rp2 = rg * 2;
            const float* wrow = ws_xs + cg * 4;

            u64 acc[4][2];
            #pragma unroll
            for (int ci = 0; ci < 4; ci++) { acc[ci][0] = 0ull; acc[ci][1] = 0ull; }

            int k0 = kq * 16;
            #pragma unroll 4
            for (int k = k0; k < k0 + 16; k++) {
                float4 wv = *(const float4*)(wrow + k * 16);
                u64 a0, a1;
                ldcg2(&g_x[g][k][rp2], a0, a1);
                u64 w;
                w = dup2(wv.x); fma2(acc[0][0],a0,w); fma2(acc[0][1],a1,w);
                w = dup2(wv.y); fma2(acc[1][0],a0,w); fma2(acc[1][1],a1,w);
                w = dup2(wv.z); fma2(acc[2][0],a0,w); fma2(acc[2][1],a1,w);
                w = dup2(wv.w); fma2(acc[3][0],a0,w); fma2(acc[3][1],a1,w);
            }
            #pragma unroll
            for (int ci = 0; ci < 4; ci++)
                #pragma unroll
                for (int q = 0; q < 2; q++) {
                    int col = cg * 4 + ci, rp = rp2 + q;
                    red[kq * 256 + rp * 16 + ((col + rp + (rp >> 2)) & 15)] = acc[ci][q];
                }
        }
        __syncthreads();
        // --------- A2 epilogue -> xs stays in registers ---------
        float xs_lo = 0.f, xs_hi = 0.f;
        if (tid < 256) {
            int sidx = crp * 16 + ((ccol + crp + (crp >> 2)) & 15);
            u64 acc = red[sidx];
            #pragma unroll
            for (int l = 1; l < 16; l++) acc = add2(acc, red[l * 256 + sidx]);
            float a0, a1; unpack2(acc, a0, a1);
            xs_lo = a0 + biasA2 + hv2_lo;
            xs_hi = a1 + biasA2 + hv2_hi;
        }
        group_barrier(g, &bar_target);   // r*s, z visible group-wide

        //==================== B GEMV: 16 cols, 32 rows, K=512 ====================
        u64 zv = 0ull;
        if (tid < 256) zv = __ldcg(&g_z[g][kcs + ccol][crp]);
        {
            int kq = wrp;
            int cg = lane & 3, rg = lane >> 2;
            int rp2 = rg * 2;
            const float* wrow = ws_us + cg * 4;

            u64 acc[4][2];
            #pragma unroll
            for (int ci = 0; ci < 4; ci++) { acc[ci][0] = 0ull; acc[ci][1] = 0ull; }

            int k0 = kq * 32;
            #pragma unroll 4
            for (int k = k0; k < k0 + 32; k++) {
                float4 wv = *(const float4*)(wrow + k * 16);
                u64 a0, a1;
                ldcg2(&g_rs[g][k][rp2], a0, a1);
                u64 w;
                w = dup2(wv.x); fma2(acc[0][0],a0,w); fma2(acc[0][1],a1,w);
                w = dup2(wv.y); fma2(acc[1][0],a0,w); fma2(acc[1][1],a1,w);
                w = dup2(wv.z); fma2(acc[2][0],a0,w); fma2(acc[2][1],a1,w);
                w = dup2(wv.w); fma2(acc[3][0],a0,w); fma2(acc[3][1],a1,w);
            }
            #pragma unroll
            for (int ci = 0; ci < 4; ci++)
                #pragma unroll
                for (int q = 0; q < 2; q++) {
                    int col = cg * 4 + ci, rp = rp2 + q;
                    red[kq * 256 + rp * 16 + ((col + rp + (rp >> 2)) & 15)] = acc[ci][q];
                }
        }
        __syncthreads();
        // --------- B epilogue: s_t (256 threads) ---------
        if (tid < 256) {
            int kglob = kcs + ccol;
            int sidx = crp * 16 + ((ccol + crp + (crp >> 2)) & 15);
            u64 acc = red[sidx];
            #pragma unroll
            for (int l = 1; l < 16; l++) acc = add2(acc, red[l * 256 + sidx]);
            float m0, m1; unpack2(acc, m0, m1);
            float z0, z1; unpack2(zv, z0, z1);
            float s1a = tanhf(xs_lo + m0);
            float s1b = tanhf(xs_hi + m1);
            float so0, so1; unpack2(soldB, so0, so1);
            g_s[g][kglob][crp] =
                pack2((1.0f - z0) * so0 + z0 * s1a, (1.0f - z1) * so1 + z1 * s1b);
        }
        group_barrier(g, &bar_target);   // s_t visible group-wide

        //==================== C GEMV: 8 cols, 32 rows, K=512 ====================
        // warp = kq (16 of 32); lane = kq2(2) x cg(2 col-groups of 4) x rg(8 row-pairs of 2)
        {
            int kq = wrp;
            int kq2 = lane >> 4, cg = (lane >> 3) & 1, rg = lane & 7;
            int rp2 = rg * 2;
            const float* wrow = ws_o + cg * 4;

            u64 acc[4][2];
            #pragma unroll
            for (int ci = 0; ci < 4; ci++) { acc[ci][0] = 0ull; acc[ci][1] = 0ull; }

            int k0 = kq * 32 + kq2 * 16;
            #pragma unroll 4
            for (int k = k0; k < k0 + 16; k++) {
                float4 wv = *(const float4*)(wrow + k * 8);
                u64 a0, a1;
                ldcg2(&g_s[g][k][rp2], a0, a1);
                u64 w;
                w = dup2(wv.x); fma2(acc[0][0],a0,w); fma2(acc[0][1],a1,w);
                w = dup2(wv.y); fma2(acc[1][0],a0,w); fma2(acc[1][1],a1,w);
                w = dup2(wv.z); fma2(acc[2][0],a0,w); fma2(acc[2][1],a1,w);
                w = dup2(wv.w); fma2(acc[3][0],a0,w); fma2(acc[3][1],a1,w);
            }
            int pk = kq * 2 + kq2;   // 0..31
            #pragma unroll
            for (int ci = 0; ci < 4; ci++)
                #pragma unroll
                for (int q = 0; q < 2; q++) {
                    int col = cg * 4 + ci, rp = rp2 + q;
                    red[pk * 128 + rp * 8 + ((col + rp + (rp >> 2)) & 7)] = acc[ci][q];
                }
        }
        __syncthreads();
        // --------- C epilogue: x_t (128 threads) ---------
        if (tid < 128) {
            int oc = o0 + ccol;
            int sidx = crp * 8 + ((ccol + crp + (crp >> 2)) & 7);
            u64 acc = red[sidx];
            #pragma unroll
            for (int l = 1; l < 32; l++) acc = add2(acc, red[l * 128 + sidx]);
            float a0, a1; unpack2(acc, a0, a1);
            float x0v = tanhf(a0 + biasC);
            float x1v = tanhf(a1 + biasC);
            g_x[g][oc][crp] = pack2(x0v, x1v);
            out[((size_t)(row0 + cr0) * TT + t) * ODIM + oc]     = x0v;
            out[((size_t)(row0 + cr0 + 1) * TT + t) * ODIM + oc] = x1v;
        }
        group_barrier(g, &bar_target);   // x_t visible group-wide
    }
}

// ---------------- launch ----------------
extern "C" void kernel_launch(void* const* d_in, const int* in_sizes, int n_in,
                              void* d_out, int out_size) {
    const float* H  = (const float*)d_in[0];
    const float* W  = (const float*)d_in[1];
    const float* Bb = (const float*)d_in[2];
    const float* U  = (const float*)d_in[3];
    const float* Wx = (const float*)d_in[4];
    const float* bx = (const float*)d_in[5];
    const float* Vr = (const float*)d_in[6];
    const float* Vz = (const float*)d_in[7];
    const float* Vs = (const float*)d_in[8];
    float* out = (float*)d_out;

    cudaFuncSetAttribute(recur_kernel, cudaFuncAttributeMaxDynamicSharedMemorySize,
                         SMEM_BYTES);

    hv_gemm<<<dim3(12, 512), 256>>>(H, Vr, Vz, Vs);
    recur_kernel<<<NCTA, NTH, SMEM_BYTES>>>(H, W, Bb, U, Wx, bx, out);
}